// round 10
// baseline (speedup 1.0000x reference)
#include <cuda_runtime.h>
#include <cuda_bf16.h>
#include <cstdint>

#define NN    10000
#define FD    128
#define DEG   32
#define OUTC  128
#define XO    120
#define KK    81
#define LDB   104          // padded K-major row stride (elements) for A and B
#define ROWB  (LDB * 2)    // 208 bytes per row

__device__ int g_nbr[NN * DEG];
__device__ int g_cnt[NN];

// ---------------- kernel 1: adjacency row -> neighbor list ----------------
__global__ void __launch_bounds__(256) build_nbr(const int* __restrict__ adj) {
    __shared__ int s_cnt;
    const int row = blockIdx.x;
    if (threadIdx.x == 0) s_cnt = 0;
    __syncthreads();
    const int4* rp = reinterpret_cast<const int4*>(adj + (size_t)row * NN);
    for (int c = threadIdx.x; c < NN / 4; c += 256) {
        int4 v = rp[c];
        int base = c * 4;
        if (v.x) { int s = atomicAdd(&s_cnt, 1); if (s < DEG) g_nbr[row * DEG + s] = base + 0; }
        if (v.y) { int s = atomicAdd(&s_cnt, 1); if (s < DEG) g_nbr[row * DEG + s] = base + 1; }
        if (v.z) { int s = atomicAdd(&s_cnt, 1); if (s < DEG) g_nbr[row * DEG + s] = base + 2; }
        if (v.w) { int s = atomicAdd(&s_cnt, 1); if (s < DEG) g_nbr[row * DEG + s] = base + 3; }
    }
    __syncthreads();
    if (threadIdx.x == 0) g_cnt[row] = (s_cnt < DEG) ? s_cnt : DEG;
}

// ---------------- warp-level mma helpers (sm_80 PTX, legal on compute_103) ----------------
__device__ __forceinline__ uint32_t smem_u32(const void* p) {
    uint32_t a;
    asm("{ .reg .u64 t; cvta.to.shared.u64 t, %1; cvt.u32.u64 %0, t; }" : "=r"(a) : "l"(p));
    return a;
}
__device__ __forceinline__ void ldsm4(uint32_t* r, uint32_t addr) {
    asm volatile("ldmatrix.sync.aligned.m8n8.x4.shared.b16 {%0,%1,%2,%3}, [%4];"
                 : "=r"(r[0]), "=r"(r[1]), "=r"(r[2]), "=r"(r[3]) : "r"(addr));
}
__device__ __forceinline__ void ldsm2(uint32_t* r, uint32_t addr) {
    asm volatile("ldmatrix.sync.aligned.m8n8.x2.shared.b16 {%0,%1}, [%2];"
                 : "=r"(r[0]), "=r"(r[1]) : "r"(addr));
}
__device__ __forceinline__ void mma16816(float* c, const uint32_t* a, const uint32_t* b) {
    asm volatile("mma.sync.aligned.m16n8k16.row.col.f32.bf16.bf16.f32 "
                 "{%0,%1,%2,%3}, {%4,%5,%6,%7}, {%8,%9}, {%0,%1,%2,%3};"
                 : "+f"(c[0]), "+f"(c[1]), "+f"(c[2]), "+f"(c[3])
                 : "r"(a[0]), "r"(a[1]), "r"(a[2]), "r"(a[3]), "r"(b[0]), "r"(b[1]));
}

// ---------------- SMEM layout (bytes) ----------------
#define OFF_SEL  0                      // 9*128 f32 = 4608
#define OFF_BIAS 4608                   // 512
#define OFF_NBR  5120                   // 128
#define OFF_CNT  5248                   // 16
#define OFF_AH   5376                   // 128*104*2 = 26624
#define OFF_AL   (OFF_AH + 26624)       // 32000
#define OFF_BH   (OFF_AL + 26624)       // 58624 : 120*104*2 = 24960
#define OFF_BL   (OFF_BH + 24960)       // 83584
#define SMEM_TOT (OFF_BL + 24960)       // 108544

__global__ void __launch_bounds__(256, 1) lgcl_mma(const float* __restrict__ nf,
                                                   const float* __restrict__ cw,
                                                   const float* __restrict__ cb,
                                                   float* __restrict__ out) {
    extern __shared__ char smc[];
    const uint32_t sa = smem_u32(smc);
    float* sel_lin = reinterpret_cast<float*>(smc + OFF_SEL);
    float* bias_s  = reinterpret_cast<float*>(smc + OFF_BIAS);
    int*   s_nbr   = reinterpret_cast<int*>(smc + OFF_NBR);
    int*   s_cnt   = reinterpret_cast<int*>(smc + OFF_CNT);

    const int tid  = threadIdx.x;
    const int wid  = tid >> 5;
    const int lane = tid & 31;

    // ---- zero A/B regions once (covers K-pad cols 81..95 forever) ----
    for (int i = tid; i < (SMEM_TOT - OFF_AH) / 4; i += 256)
        reinterpret_cast<uint32_t*>(smc + OFF_AH)[i] = 0;
    if (tid < OUTC) bias_s[tid] = cb[tid];
    __syncthreads();

    // ---- stage weights once: A[m=o][k=c*9+t], bf16 hi/lo split ----
    for (int idx = tid; idx < OUTC * KK; idx += 256) {
        int m = idx / KK, k = idx - m * KK;
        float v = cw[idx];
        __nv_bfloat16 hi = __float2bfloat16(v);
        __nv_bfloat16 lo = __float2bfloat16(v - __bfloat162float(hi));
        uint32_t off = (uint32_t)(m * LDB + k) * 2;
        *reinterpret_cast<__nv_bfloat16*>(smc + OFF_AH + off) = hi;
        *reinterpret_cast<__nv_bfloat16*>(smc + OFF_AL + off) = lo;
    }
    __syncthreads();

    // per-lane ldmatrix address offsets (bytes)
    const uint32_t offA = (uint32_t)(((lane & 15) * LDB + ((lane >> 4) << 3)) * 2);
    const uint32_t offB = (uint32_t)(((((lane >> 4) << 3) + (lane & 7)) * LDB + (((lane >> 3) & 1) << 3)) * 2);
    const uint32_t offB2 = (uint32_t)(((lane & 7) * LDB + (((lane >> 3) & 1) << 3)) * 2);
    const uint32_t aBaseH = sa + OFF_AH + wid * 16 * ROWB + offA;
    const uint32_t aBaseL = sa + OFF_AL + wid * 16 * ROWB + offA;

    for (int node = blockIdx.x; node < NN; node += gridDim.x) {
        // ---- stage neighbor list ----
        if (tid < DEG) s_nbr[tid] = g_nbr[node * DEG + tid];
        if (tid == 64) *s_cnt = g_cnt[node];
        __syncthreads();

        // ---- per-column top-8 (threads 0..127), 8-deep LDG prefetch ----
        if (tid < FD) {
            const int j = tid;
            const int cnt = *s_cnt;
            float tk[8];
#pragma unroll
            for (int k = 0; k < 8; k++) tk[k] = -1e30f;
            int i = 0;
            for (; i + 8 <= cnt; i += 8) {
                float v[8];
#pragma unroll
                for (int q = 0; q < 8; q++)
                    v[q] = __ldg(nf + (size_t)s_nbr[i + q] * FD + j);
#pragma unroll
                for (int q = 0; q < 8; q++) {
                    float x = v[q];
#pragma unroll
                    for (int k = 0; k < 8; k++) { float mx = fmaxf(tk[k], x); x = fminf(tk[k], x); tk[k] = mx; }
                }
            }
            for (; i < cnt; i++) {
                float x = __ldg(nf + (size_t)s_nbr[i] * FD + j);
#pragma unroll
                for (int k = 0; k < 8; k++) { float mx = fmaxf(tk[k], x); x = fminf(tk[k], x); tk[k] = mx; }
            }
            for (i = cnt; i < 8; i++) {  // torch zero-pads rows before topk
                float x = 0.0f;
#pragma unroll
                for (int k = 0; k < 8; k++) { float mx = fmaxf(tk[k], x); x = fminf(tk[k], x); tk[k] = mx; }
            }
            sel_lin[j] = nf[(size_t)node * FD + j];
#pragma unroll
            for (int k = 0; k < 8; k++) sel_lin[(1 + k) * FD + j] = tk[k];
        }
        __syncthreads();

        // ---- B im2col fill: B[x][k=c*9+t] = sel[c][x+t], bf16 hi/lo ----
        for (int idx = tid; idx < XO * KK; idx += 256) {
            int x = idx / KK, k = idx - x * KK;
            int c = k / 9, t = k - c * 9;
            float v = sel_lin[c * FD + x + t];
            __nv_bfloat16 hi = __float2bfloat16(v);
            __nv_bfloat16 lo = __float2bfloat16(v - __bfloat162float(hi));
            uint32_t off = (uint32_t)(x * LDB + k) * 2;
            *reinterpret_cast<__nv_bfloat16*>(smc + OFF_BH + off) = hi;
            *reinterpret_cast<__nv_bfloat16*>(smc + OFF_BL + off) = lo;
        }
        __syncthreads();

        // ---- GEMM: warp = 16 M-rows x 120 N; 3-pass bf16 split, 6 k-steps ----
        float C[15][4];
#pragma unroll
        for (int t = 0; t < 15; t++) { C[t][0] = C[t][1] = C[t][2] = C[t][3] = 0.f; }

#pragma unroll
        for (int p = 0; p < 3; p++) {
            const uint32_t aB = (p == 1) ? aBaseL : aBaseH;
            const uint32_t bB = sa + ((p == 2) ? OFF_BL : OFF_BH);
#pragma unroll
            for (int s = 0; s < 6; s++) {
                uint32_t a[4];
                ldsm4(a, aB + s * 32);
#pragma unroll
                for (int g = 0; g < 7; g++) {
                    uint32_t b[4];
                    ldsm4(b, bB + g * 16 * ROWB + offB + s * 32);
                    mma16816(C[2 * g + 0], a, b + 0);
                    mma16816(C[2 * g + 1], a, b + 2);
                }
                uint32_t b2[2];
                ldsm2(b2, bB + 112 * ROWB + offB2 + s * 32);
                mma16816(C[14], a, b2);
            }
        }

        // ---- epilogue: +bias, float2 stores ----
        {
            const int o0 = wid * 16 + (lane >> 2);
            const int o1 = o0 + 8;
            const float b0 = bias_s[o0], b1 = bias_s[o1];
            float* base = out + (size_t)node * (OUTC * XO);
            float* p0 = base + o0 * XO + 2 * (lane & 3);
            float* p1 = base + o1 * XO + 2 * (lane & 3);
#pragma unroll
            for (int t = 0; t < 15; t++) {
                *reinterpret_cast<float2*>(p0 + t * 8) = make_float2(C[t][0] + b0, C[t][1] + b0);
                *reinterpret_cast<float2*>(p1 + t * 8) = make_float2(C[t][2] + b1, C[t][3] + b1);
            }
        }
        __syncthreads();   // all warps done reading B/sel before next node
    }
}

extern "C" void kernel_launch(void* const* d_in, const int* in_sizes, int n_in,
                              void* d_out, int out_size) {
    const float* nf  = (const float*)d_in[0];
    const int*   adj = (const int*)d_in[1];
    const float* cw  = (const float*)d_in[2];
    const float* cb  = (const float*)d_in[3];
    float* out = (float*)d_out;
    (void)in_sizes; (void)n_in; (void)out_size;

    cudaFuncSetAttribute(lgcl_mma, cudaFuncAttributeMaxDynamicSharedMemorySize, SMEM_TOT);

    build_nbr<<<NN, 256>>>(adj);
    lgcl_mma<<<152, 256, SMEM_TOT>>>(nf, cw, cb, out);
}

// round 11
// speedup vs baseline: 2.0102x; 2.0102x over previous
#include <cuda_runtime.h>
#include <cuda_bf16.h>
#include <cstdint>

#define NN    10000
#define FD    128
#define DEG   32
#define OUTC  128
#define XO    120
#define KK    81
#define LDB   104          // K-major row stride (elements); LDB*2=208 B, 16B-aligned rows
#define ROWB  (LDB * 2)

__device__ int g_nbr[NN * DEG];
__device__ int g_cnt[NN];

// ---------------- kernel 1: adjacency row -> neighbor list ----------------
__global__ void __launch_bounds__(256) build_nbr(const int* __restrict__ adj) {
    __shared__ int s_cnt;
    const int row = blockIdx.x;
    if (threadIdx.x == 0) s_cnt = 0;
    __syncthreads();
    const int4* rp = reinterpret_cast<const int4*>(adj + (size_t)row * NN);
    for (int c = threadIdx.x; c < NN / 4; c += 256) {
        int4 v = rp[c];
        int base = c * 4;
        if (v.x) { int s = atomicAdd(&s_cnt, 1); if (s < DEG) g_nbr[row * DEG + s] = base + 0; }
        if (v.y) { int s = atomicAdd(&s_cnt, 1); if (s < DEG) g_nbr[row * DEG + s] = base + 1; }
        if (v.z) { int s = atomicAdd(&s_cnt, 1); if (s < DEG) g_nbr[row * DEG + s] = base + 2; }
        if (v.w) { int s = atomicAdd(&s_cnt, 1); if (s < DEG) g_nbr[row * DEG + s] = base + 3; }
    }
    __syncthreads();
    if (threadIdx.x == 0) g_cnt[row] = (s_cnt < DEG) ? s_cnt : DEG;
}

// ---------------- warp-level mma helpers (sm_80 PTX, legal on compute_103) ----------------
__device__ __forceinline__ uint32_t smem_u32(const void* p) {
    uint32_t a;
    asm("{ .reg .u64 t; cvta.to.shared.u64 t, %1; cvt.u32.u64 %0, t; }" : "=r"(a) : "l"(p));
    return a;
}
__device__ __forceinline__ void ldsm4(uint32_t* r, uint32_t addr) {
    asm volatile("ldmatrix.sync.aligned.m8n8.x4.shared.b16 {%0,%1,%2,%3}, [%4];"
                 : "=r"(r[0]), "=r"(r[1]), "=r"(r[2]), "=r"(r[3]) : "r"(addr));
}
__device__ __forceinline__ void ldsm2(uint32_t* r, uint32_t addr) {
    asm volatile("ldmatrix.sync.aligned.m8n8.x2.shared.b16 {%0,%1}, [%2];"
                 : "=r"(r[0]), "=r"(r[1]) : "r"(addr));
}
__device__ __forceinline__ void mma16816(float* c, const uint32_t* a, const uint32_t* b) {
    asm volatile("mma.sync.aligned.m16n8k16.row.col.f32.bf16.bf16.f32 "
                 "{%0,%1,%2,%3}, {%4,%5,%6,%7}, {%8,%9}, {%0,%1,%2,%3};"
                 : "+f"(c[0]), "+f"(c[1]), "+f"(c[2]), "+f"(c[3])
                 : "r"(a[0]), "r"(a[1]), "r"(a[2]), "r"(a[3]), "r"(b[0]), "r"(b[1]));
}
#define BAR_SYNC(id) asm volatile("bar.sync %0, %1;" :: "r"(id), "r"(256) : "memory")

// ---------------- SMEM layout (bytes) ----------------
#define OFF_BIAS 0                       // 512
#define OFF_AH   1024                    // 128*208 = 26624
#define OFF_AL   (OFF_AH + 26624)        // 27648
#define OFF_B    (OFF_AL + 26624)        // 54272 : 2 bufs x (BH 24960 + BL 24960)
#define BUF_STRIDE (2 * 24960)           // 49920
#define SMEM_TOT (OFF_B + 2 * BUF_STRIDE)  // 154112

__global__ void __launch_bounds__(256, 1) lgcl_ws(const float* __restrict__ nf,
                                                  const float* __restrict__ cw,
                                                  const float* __restrict__ cb,
                                                  float* __restrict__ out) {
    extern __shared__ char smc[];
    const uint32_t sa = smem_u32(smc);
    float* bias_s = reinterpret_cast<float*>(smc + OFF_BIAS);

    const int tid  = threadIdx.x;
    const int wid  = tid >> 5;
    const int lane = tid & 31;

    // ---- init: zero A+B (covers K-pad cols 81..95 forever), stage bias+weights ----
    for (int i = tid; i < (SMEM_TOT - OFF_AH) / 4; i += 256)
        reinterpret_cast<uint32_t*>(smc + OFF_AH)[i] = 0;
    if (tid < OUTC) bias_s[tid] = cb[tid];
    for (int idx = tid; idx < OUTC * KK; idx += 256) {
        int m = idx / KK, k = idx - m * KK;
        float v = cw[idx];
        __nv_bfloat16 hi = __float2bfloat16(v);
        __nv_bfloat16 lo = __float2bfloat16(v - __bfloat162float(hi));
        uint32_t off = (uint32_t)(m * LDB + k) * 2;
        *reinterpret_cast<__nv_bfloat16*>(smc + OFF_AH + off) = hi;
        *reinterpret_cast<__nv_bfloat16*>(smc + OFF_AL + off) = lo;
    }
    __syncthreads();

    int it = 0;

    if (wid >= 4) {
        // ================= PRODUCER (warps 4..7): topk -> direct im2col scatter =========
        const int j = tid - 128;                       // column 0..127
        for (int node = blockIdx.x; node < NN; node += gridDim.x, ++it) {
            const int buf = it & 1;
            char* bh = smc + OFF_B + buf * BUF_STRIDE;
            char* bl = bh + 24960;

            const int cnt = g_cnt[node];
            float tk[8];
#pragma unroll
            for (int k = 0; k < 8; k++) tk[k] = -1e30f;
            int i = 0;
            for (; i + 8 <= cnt; i += 8) {
                int nb8[8];
#pragma unroll
                for (int q = 0; q < 8; q++) nb8[q] = g_nbr[node * DEG + i + q];
                float v[8];
#pragma unroll
                for (int q = 0; q < 8; q++) v[q] = __ldg(nf + (size_t)nb8[q] * FD + j);
#pragma unroll
                for (int q = 0; q < 8; q++) {
                    float x = v[q];
#pragma unroll
                    for (int k = 0; k < 8; k++) { float mx = fmaxf(tk[k], x); x = fminf(tk[k], x); tk[k] = mx; }
                }
            }
            for (; i < cnt; i++) {
                float x = __ldg(nf + (size_t)g_nbr[node * DEG + i] * FD + j);
#pragma unroll
                for (int k = 0; k < 8; k++) { float mx = fmaxf(tk[k], x); x = fminf(tk[k], x); tk[k] = mx; }
            }
            for (i = cnt; i < 8; i++) {                // torch zero-pads rows before topk
                float x = 0.0f;
#pragma unroll
                for (int k = 0; k < 8; k++) { float mx = fmaxf(tk[k], x); x = fminf(tk[k], x); tk[k] = mx; }
            }

            float vals[9];
            vals[0] = nf[(size_t)node * FD + j];       // channel 0: self
#pragma unroll
            for (int k = 0; k < 8; k++) vals[1 + k] = tk[k];

            // column j of sel feeds B[x = j - t][k = c*9 + t], t in [0,8]
#pragma unroll
            for (int c = 0; c < 9; c++) {
                float v = vals[c];
                __nv_bfloat16 hi = __float2bfloat16(v);
                __nv_bfloat16 lo = __float2bfloat16(v - __bfloat162float(hi));
#pragma unroll
                for (int t = 0; t < 9; t++) {
                    int x = j - t;
                    if (x >= 0 && x < XO) {
                        uint32_t off = (uint32_t)(x * LDB + c * 9 + t) * 2;
                        *reinterpret_cast<__nv_bfloat16*>(bh + off) = hi;
                        *reinterpret_cast<__nv_bfloat16*>(bl + off) = lo;
                    }
                }
            }
            BAR_SYNC(1 + buf);                         // publish buffer `buf`
        }
    } else {
        // ================= CONSUMER (warps 0..3): 32 M-rows each, 3-pass bf16 GEMM ======
        const uint32_t offA = (uint32_t)(((lane & 15) * LDB + ((lane >> 4) << 3)) * 2);
        const uint32_t offB = (uint32_t)(((((lane >> 4) << 3) + (lane & 7)) * LDB + (((lane >> 3) & 1) << 3)) * 2);
        const uint32_t offB2 = (uint32_t)(((lane & 7) * LDB + (((lane >> 3) & 1) << 3)) * 2);
        const uint32_t aH = sa + OFF_AH + wid * 32 * ROWB + offA;
        const uint32_t aL = sa + OFF_AL + wid * 32 * ROWB + offA;

        for (int node = blockIdx.x; node < NN; node += gridDim.x, ++it) {
            const int buf = it & 1;
            BAR_SYNC(1 + buf);                         // wait buffer `buf` full

            const uint32_t bhA = sa + OFF_B + buf * BUF_STRIDE;

            float C[2][15][4];
#pragma unroll
            for (int mt = 0; mt < 2; mt++)
#pragma unroll
                for (int t = 0; t < 15; t++)
                    C[mt][t][0] = C[mt][t][1] = C[mt][t][2] = C[mt][t][3] = 0.f;

#pragma unroll
            for (int p = 0; p < 3; p++) {
                const uint32_t aB = (p == 1) ? aL : aH;
                const uint32_t bB = bhA + ((p == 2) ? 24960u : 0u);
#pragma unroll
                for (int s = 0; s < 6; s++) {
                    uint32_t a0[4], a1[4];
                    ldsm4(a0, aB + s * 32);
                    ldsm4(a1, aB + 16 * ROWB + s * 32);
#pragma unroll
                    for (int g = 0; g < 7; g++) {
                        uint32_t b[4];
                        ldsm4(b, bB + g * 16 * ROWB + offB + s * 32);
                        mma16816(C[0][2 * g + 0], a0, b + 0);
                        mma16816(C[0][2 * g + 1], a0, b + 2);
                        mma16816(C[1][2 * g + 0], a1, b + 0);
                        mma16816(C[1][2 * g + 1], a1, b + 2);
                    }
                    uint32_t b2[2];
                    ldsm2(b2, bB + 112 * ROWB + offB2 + s * 32);
                    mma16816(C[0][14], a0, b2);
                    mma16816(C[1][14], a1, b2);
                }
            }

            // epilogue: +bias, float2 stores
            float* base = out + (size_t)node * (OUTC * XO);
#pragma unroll
            for (int mt = 0; mt < 2; mt++) {
                const int o0 = wid * 32 + mt * 16 + (lane >> 2);
                const int o1 = o0 + 8;
                const float b0 = bias_s[o0], b1 = bias_s[o1];
                float* p0 = base + o0 * XO + 2 * (lane & 3);
                float* p1 = base + o1 * XO + 2 * (lane & 3);
#pragma unroll
                for (int t = 0; t < 15; t++) {
                    *reinterpret_cast<float2*>(p0 + t * 8) =
                        make_float2(C[mt][t][0] + b0, C[mt][t][1] + b0);
                    *reinterpret_cast<float2*>(p1 + t * 8) =
                        make_float2(C[mt][t][2] + b1, C[mt][t][3] + b1);
                }
            }
            // buffer `buf` becomes reusable once we arrive at its barrier next round;
            // producer won't refill it until after this consumer arrives at BAR(1+buf)
            // again, which happens strictly after the MMA above read it.
        }
    }
}

extern "C" void kernel_launch(void* const* d_in, const int* in_sizes, int n_in,
                              void* d_out, int out_size) {
    const float* nf  = (const float*)d_in[0];
    const int*   adj = (const int*)d_in[1];
    const float* cw  = (const float*)d_in[2];
    const float* cb  = (const float*)d_in[3];
    float* out = (float*)d_out;
    (void)in_sizes; (void)n_in; (void)out_size;

    cudaFuncSetAttribute(lgcl_ws, cudaFuncAttributeMaxDynamicSharedMemorySize, SMEM_TOT);

    build_nbr<<<NN, 256>>>(adj);
    lgcl_ws<<<152, 256, SMEM_TOT>>>(nf, cw, cb, out);
}